// round 6
// baseline (speedup 1.0000x reference)
#include <cuda_runtime.h>
#include <cuda_bf16.h>
#include <cstdint>

// Problem constants (shapes fixed by the dataset; sizes re-derived from in_sizes)
#define MAX_NODES 100000
#define MAX_EDGES 1600000
#define IN_DIM    64
#define HID_DIM   32
#define SCAN_THREADS 1024

// Scratch (allocation-free rule: __device__ globals)
__device__ int   g_deg_out[MAX_NODES];
__device__ int   g_deg_in [MAX_NODES];
__device__ int   g_row_ptr[MAX_NODES + 1];
__device__ int   g_cursor [MAX_NODES];
__device__ int   g_csr_src[MAX_EDGES];
__device__ float g_h      [MAX_NODES * HID_DIM];   // (X@W) * norm_src

// ---------------------------------------------------------------------------
// K0: zero degree counters (cursor/row_ptr are fully rewritten by the scan)
// ---------------------------------------------------------------------------
__global__ void k_zero_deg(int n) {
    int i = blockIdx.x * blockDim.x + threadIdx.x;
    if (i < n) { g_deg_out[i] = 0; g_deg_in[i] = 0; }
}

// ---------------------------------------------------------------------------
// K1: in-degree counts (int RED, 1.6M lanes)
// ---------------------------------------------------------------------------
__global__ void k_deg_in(const int* __restrict__ dst, int E) {
    int i = blockIdx.x * blockDim.x + threadIdx.x;
    if (i < E) atomicAdd(&g_deg_in[__ldg(dst + i)], 1);
}

// ---------------------------------------------------------------------------
// K2: exclusive scan of deg_in -> row_ptr (and cursor copy). Single block.
//     Each thread sums a contiguous chunk, block-scans the partials, then
//     writes its chunk's running prefix.
// ---------------------------------------------------------------------------
__global__ void k_scan(int n) {
    __shared__ int sp[SCAN_THREADS];
    int t = threadIdx.x;
    int C = (n + SCAN_THREADS - 1) / SCAN_THREADS;
    int lo = t * C;
    int hi = min(lo + C, n);

    int s = 0;
    for (int i = lo; i < hi; i++) s += g_deg_in[i];
    sp[t] = s;
    __syncthreads();

    // Hillis-Steele inclusive scan over 1024 partials
    for (int off = 1; off < SCAN_THREADS; off <<= 1) {
        int v = (t >= off) ? sp[t - off] : 0;
        __syncthreads();
        sp[t] += v;
        __syncthreads();
    }

    int run = (t == 0) ? 0 : sp[t - 1];
    for (int i = lo; i < hi; i++) {
        g_row_ptr[i] = run;
        g_cursor[i]  = run;
        run += g_deg_in[i];
    }
    if (t == SCAN_THREADS - 1) g_row_ptr[n] = sp[SCAN_THREADS - 1];
}

// ---------------------------------------------------------------------------
// K3: CSR fill (counting-sort placement) fused with out-degree counting.
// ---------------------------------------------------------------------------
__global__ void k_fill(const int* __restrict__ src, const int* __restrict__ dst, int E) {
    int i = blockIdx.x * blockDim.x + threadIdx.x;
    if (i >= E) return;
    int s = __ldg(src + i);
    int d = __ldg(dst + i);
    int pos = atomicAdd(&g_cursor[d], 1);
    g_csr_src[pos] = s;
    atomicAdd(&g_deg_out[s], 1);
}

// ---------------------------------------------------------------------------
// K4: h = (X @ W) * rsqrt(max(deg_out,1))
//     One row per thread; W staged in smem (all-thread broadcast reads).
// ---------------------------------------------------------------------------
__global__ void k_gemm_norm(const float* __restrict__ X,
                            const float* __restrict__ W,
                            int n) {
    __shared__ float sW[IN_DIM * HID_DIM];   // 8 KB
    for (int i = threadIdx.x; i < IN_DIM * HID_DIM; i += blockDim.x)
        sW[i] = W[i];
    __syncthreads();

    int r = blockIdx.x * blockDim.x + threadIdx.x;
    if (r >= n) return;

    float acc[HID_DIM];
#pragma unroll
    for (int j = 0; j < HID_DIM; j++) acc[j] = 0.f;

    const float4* xr = reinterpret_cast<const float4*>(X + (size_t)r * IN_DIM);
#pragma unroll 4
    for (int k4 = 0; k4 < IN_DIM / 4; k4++) {
        float4 x = __ldg(xr + k4);
        int k = k4 * 4;
#pragma unroll
        for (int j = 0; j < HID_DIM; j++) {
            acc[j] = fmaf(x.x, sW[(k + 0) * HID_DIM + j],
                     fmaf(x.y, sW[(k + 1) * HID_DIM + j],
                     fmaf(x.z, sW[(k + 2) * HID_DIM + j],
                     fmaf(x.w, sW[(k + 3) * HID_DIM + j], acc[j]))));
        }
    }

    float nrm = rsqrtf(fmaxf((float)g_deg_out[r], 1.0f));
    float4* hr = reinterpret_cast<float4*>(g_h + (size_t)r * HID_DIM);
#pragma unroll
    for (int j4 = 0; j4 < HID_DIM / 4; j4++) {
        float4 v;
        v.x = acc[j4 * 4 + 0] * nrm;
        v.y = acc[j4 * 4 + 1] * nrm;
        v.z = acc[j4 * 4 + 2] * nrm;
        v.w = acc[j4 * 4 + 3] * nrm;
        hr[j4] = v;
    }
}

// ---------------------------------------------------------------------------
// K5: pull-style aggregation + finalize. One warp per dst node.
//     Lane layout: g = lane>>3 (edge sub-slot, 4 edges/iter), p = lane&7
//     (float4 slice of the 32-float row). Warp-uniform degree loop, shfl
//     reduction across g, fused norm_dst + bias + relu, single 128B store.
//     No atomics anywhere.
// ---------------------------------------------------------------------------
__global__ void k_aggregate(float* __restrict__ out,
                            const float* __restrict__ b,
                            int n) {
    int warp = (blockIdx.x * blockDim.x + threadIdx.x) >> 5;
    if (warp >= n) return;
    int lane = threadIdx.x & 31;
    int p = lane & 7;
    int g = lane >> 3;

    int start = __ldg(&g_row_ptr[warp]);
    int end   = __ldg(&g_row_ptr[warp + 1]);

    const float4* h4 = reinterpret_cast<const float4*>(g_h);
    float4 acc = make_float4(0.f, 0.f, 0.f, 0.f);

    for (int j = start + g; j < end; j += 4) {
        int s = __ldg(&g_csr_src[j]);
        float4 v = __ldg(h4 + (size_t)s * (HID_DIM / 4) + p);
        acc.x += v.x; acc.y += v.y; acc.z += v.z; acc.w += v.w;
    }

    // Reduce the 4 edge sub-slots (lanes p, p+8, p+16, p+24)
#pragma unroll
    for (int off = 16; off >= 8; off >>= 1) {
        acc.x += __shfl_down_sync(0xffffffffu, acc.x, off);
        acc.y += __shfl_down_sync(0xffffffffu, acc.y, off);
        acc.z += __shfl_down_sync(0xffffffffu, acc.z, off);
        acc.w += __shfl_down_sync(0xffffffffu, acc.w, off);
    }

    if (g == 0) {
        float nrm = rsqrtf(fmaxf((float)(end - start), 1.0f));
        float4 bb = __ldg(reinterpret_cast<const float4*>(b) + p);
        float4 v;
        v.x = fmaxf(acc.x * nrm + bb.x, 0.f);
        v.y = fmaxf(acc.y * nrm + bb.y, 0.f);
        v.z = fmaxf(acc.z * nrm + bb.z, 0.f);
        v.w = fmaxf(acc.w * nrm + bb.w, 0.f);
        reinterpret_cast<float4*>(out)[(size_t)warp * (HID_DIM / 4) + p] = v;
    }
}

// ---------------------------------------------------------------------------
extern "C" void kernel_launch(void* const* d_in, const int* in_sizes, int n_in,
                              void* d_out, int out_size) {
    const float* features = (const float*)d_in[0];
    const int*   src      = (const int*)  d_in[1];
    const int*   dst      = (const int*)  d_in[2];
    const float* W        = (const float*)d_in[3];
    const float* b        = (const float*)d_in[4];
    float*       out      = (float*)d_out;

    int n = in_sizes[0] / IN_DIM;   // 100000
    int E = in_sizes[1];            // 1600000

    const int B = 256;

    // K0: zero degree counters
    k_zero_deg<<<(n + B - 1) / B, B>>>(n);

    // K1: in-degree histogram
    k_deg_in<<<(E + B - 1) / B, B>>>(dst, E);

    // K2: exclusive scan -> row_ptr, cursor
    k_scan<<<1, SCAN_THREADS>>>(n);

    // K3: CSR fill + out-degree histogram
    k_fill<<<(E + B - 1) / B, B>>>(src, dst, E);

    // K4: gemm + src-norm
    k_gemm_norm<<<(n + B - 1) / B, B>>>(features, W, n);

    // K5: pull aggregation + norm_dst + bias + relu (one warp per node)
    long long threads5 = (long long)n * 32;
    k_aggregate<<<(int)((threads5 + B - 1) / B), B>>>(out, b, n);
}

// round 7
// speedup vs baseline: 2.4994x; 2.4994x over previous
#include <cuda_runtime.h>
#include <cuda_bf16.h>
#include <cstdint>

// Problem constants (shapes fixed by the dataset; sizes re-derived from in_sizes)
#define MAX_NODES 100000
#define MAX_EDGES 1600000
#define IN_DIM    64
#define HID_DIM   32
#define SCAN_TILE 1024            // elems per block in phase A (256 thr x 4)
#define MAX_PARTIALS 128          // supports n <= 131072

// Scratch (allocation-free rule: __device__ globals)
__device__ int   g_deg_out[MAX_NODES];
__device__ int   g_deg_in [MAX_NODES];
__device__ int   g_row_ptr[MAX_NODES + 1];
__device__ int   g_cursor [MAX_NODES];
__device__ int   g_partial[MAX_PARTIALS];
__device__ int   g_csr_src[MAX_EDGES];
__device__ float g_h      [MAX_NODES * HID_DIM];   // (X@W) * norm_src

// ---------------------------------------------------------------------------
// K0: zero degree counters
// ---------------------------------------------------------------------------
__global__ void k_zero_deg(int n) {
    int i = blockIdx.x * blockDim.x + threadIdx.x;
    if (i < n) { g_deg_out[i] = 0; g_deg_in[i] = 0; }
}

// ---------------------------------------------------------------------------
// K1: in-degree counts (int RED, 1.6M lanes)
// ---------------------------------------------------------------------------
__global__ void k_deg_in(const int* __restrict__ dst, int E) {
    int i = blockIdx.x * blockDim.x + threadIdx.x;
    if (i < E) atomicAdd(&g_deg_in[__ldg(dst + i)], 1);
}

// ---------------------------------------------------------------------------
// K2a: per-block local exclusive scan. Each thread: 4 coalesced elems (int4).
//      Writes block-local exclusive prefixes into g_row_ptr and the block
//      total into g_partial[blockIdx].
// ---------------------------------------------------------------------------
__global__ void k_scan_local(int n) {
    __shared__ int sw[256];
    int t = threadIdx.x;
    int idx = blockIdx.x * SCAN_TILE + t * 4;

    int v0 = 0, v1 = 0, v2 = 0, v3 = 0;
    if (idx + 3 < n) {
        int4 v = *reinterpret_cast<const int4*>(g_deg_in + idx);
        v0 = v.x; v1 = v.y; v2 = v.z; v3 = v.w;
    } else {
        if (idx + 0 < n) v0 = g_deg_in[idx + 0];
        if (idx + 1 < n) v1 = g_deg_in[idx + 1];
        if (idx + 2 < n) v2 = g_deg_in[idx + 2];
    }

    sw[t] = v0 + v1 + v2 + v3;
    __syncthreads();
    // Hillis-Steele inclusive scan over 256 thread sums
    for (int off = 1; off < 256; off <<= 1) {
        int u = (t >= off) ? sw[t - off] : 0;
        __syncthreads();
        sw[t] += u;
        __syncthreads();
    }
    int excl = (t == 0) ? 0 : sw[t - 1];

    if (idx + 0 < n) g_row_ptr[idx + 0] = excl;
    if (idx + 1 < n) g_row_ptr[idx + 1] = excl + v0;
    if (idx + 2 < n) g_row_ptr[idx + 2] = excl + v0 + v1;
    if (idx + 3 < n) g_row_ptr[idx + 3] = excl + v0 + v1 + v2;
    if (t == 255) g_partial[blockIdx.x] = sw[255];
}

// ---------------------------------------------------------------------------
// K2b: exclusive scan of block partials (nb <= 128). One block.
// ---------------------------------------------------------------------------
__global__ void k_scan_partials(int nb) {
    __shared__ int sp[MAX_PARTIALS];
    int t = threadIdx.x;
    sp[t] = (t < nb) ? g_partial[t] : 0;
    __syncthreads();
    for (int off = 1; off < MAX_PARTIALS; off <<= 1) {
        int u = (t >= off) ? sp[t - off] : 0;
        __syncthreads();
        sp[t] += u;
        __syncthreads();
    }
    if (t < nb) g_partial[t] = (t == 0) ? 0 : sp[t - 1];
}

// ---------------------------------------------------------------------------
// K2c: add block offsets; copy to cursor; cap row_ptr[n]=E.
// ---------------------------------------------------------------------------
__global__ void k_scan_addoff(int n, int E) {
    int i = blockIdx.x * blockDim.x + threadIdx.x;
    if (i < n) {
        int v = g_row_ptr[i] + g_partial[i / SCAN_TILE];
        g_row_ptr[i] = v;
        g_cursor[i]  = v;
    }
    if (i == 0) g_row_ptr[n] = E;
}

// ---------------------------------------------------------------------------
// K3: CSR fill (counting-sort placement) fused with out-degree counting.
//     2 independent edges per thread to double atomic MLP.
// ---------------------------------------------------------------------------
__global__ void k_fill(const int* __restrict__ src, const int* __restrict__ dst, int E) {
    int i = (blockIdx.x * blockDim.x + threadIdx.x) * 2;
    if (i >= E) return;
    int s0 = __ldg(src + i);
    int d0 = __ldg(dst + i);
    int has1 = (i + 1 < E);
    int s1 = has1 ? __ldg(src + i + 1) : 0;
    int d1 = has1 ? __ldg(dst + i + 1) : 0;

    int p0 = atomicAdd(&g_cursor[d0], 1);
    int p1 = has1 ? atomicAdd(&g_cursor[d1], 1) : 0;
    g_csr_src[p0] = s0;
    if (has1) g_csr_src[p1] = s1;
    atomicAdd(&g_deg_out[s0], 1);
    if (has1) atomicAdd(&g_deg_out[s1], 1);
}

// ---------------------------------------------------------------------------
// K4: h = (X @ W) * rsqrt(max(deg_out,1))
// ---------------------------------------------------------------------------
__global__ void k_gemm_norm(const float* __restrict__ X,
                            const float* __restrict__ W,
                            int n) {
    __shared__ float sW[IN_DIM * HID_DIM];   // 8 KB
    for (int i = threadIdx.x; i < IN_DIM * HID_DIM; i += blockDim.x)
        sW[i] = W[i];
    __syncthreads();

    int r = blockIdx.x * blockDim.x + threadIdx.x;
    if (r >= n) return;

    float acc[HID_DIM];
#pragma unroll
    for (int j = 0; j < HID_DIM; j++) acc[j] = 0.f;

    const float4* xr = reinterpret_cast<const float4*>(X + (size_t)r * IN_DIM);
#pragma unroll 4
    for (int k4 = 0; k4 < IN_DIM / 4; k4++) {
        float4 x = __ldg(xr + k4);
        int k = k4 * 4;
#pragma unroll
        for (int j = 0; j < HID_DIM; j++) {
            acc[j] = fmaf(x.x, sW[(k + 0) * HID_DIM + j],
                     fmaf(x.y, sW[(k + 1) * HID_DIM + j],
                     fmaf(x.z, sW[(k + 2) * HID_DIM + j],
                     fmaf(x.w, sW[(k + 3) * HID_DIM + j], acc[j]))));
        }
    }

    float nrm = rsqrtf(fmaxf((float)g_deg_out[r], 1.0f));
    float4* hr = reinterpret_cast<float4*>(g_h + (size_t)r * HID_DIM);
#pragma unroll
    for (int j4 = 0; j4 < HID_DIM / 4; j4++) {
        float4 v;
        v.x = acc[j4 * 4 + 0] * nrm;
        v.y = acc[j4 * 4 + 1] * nrm;
        v.z = acc[j4 * 4 + 2] * nrm;
        v.w = acc[j4 * 4 + 3] * nrm;
        hr[j4] = v;
    }
}

// ---------------------------------------------------------------------------
// K5: pull-style aggregation + finalize. One warp per dst node.
//     g = lane>>3 (4 edges/iter), p = lane&7 (float4 slice). Shfl reduce,
//     fused norm_dst + bias + relu, single 128B store. No atomics.
// ---------------------------------------------------------------------------
__global__ void k_aggregate(float* __restrict__ out,
                            const float* __restrict__ b,
                            int n) {
    int warp = (blockIdx.x * blockDim.x + threadIdx.x) >> 5;
    if (warp >= n) return;
    int lane = threadIdx.x & 31;
    int p = lane & 7;
    int g = lane >> 3;

    int start = __ldg(&g_row_ptr[warp]);
    int end   = __ldg(&g_row_ptr[warp + 1]);

    const float4* h4 = reinterpret_cast<const float4*>(g_h);
    float4 acc = make_float4(0.f, 0.f, 0.f, 0.f);

    for (int j = start + g; j < end; j += 4) {
        int s = __ldg(&g_csr_src[j]);
        float4 v = __ldg(h4 + (size_t)s * (HID_DIM / 4) + p);
        acc.x += v.x; acc.y += v.y; acc.z += v.z; acc.w += v.w;
    }

#pragma unroll
    for (int off = 16; off >= 8; off >>= 1) {
        acc.x += __shfl_down_sync(0xffffffffu, acc.x, off);
        acc.y += __shfl_down_sync(0xffffffffu, acc.y, off);
        acc.z += __shfl_down_sync(0xffffffffu, acc.z, off);
        acc.w += __shfl_down_sync(0xffffffffu, acc.w, off);
    }

    if (g == 0) {
        float nrm = rsqrtf(fmaxf((float)(end - start), 1.0f));
        float4 bb = __ldg(reinterpret_cast<const float4*>(b) + p);
        float4 v;
        v.x = fmaxf(acc.x * nrm + bb.x, 0.f);
        v.y = fmaxf(acc.y * nrm + bb.y, 0.f);
        v.z = fmaxf(acc.z * nrm + bb.z, 0.f);
        v.w = fmaxf(acc.w * nrm + bb.w, 0.f);
        reinterpret_cast<float4*>(out)[(size_t)warp * (HID_DIM / 4) + p] = v;
    }
}

// ---------------------------------------------------------------------------
extern "C" void kernel_launch(void* const* d_in, const int* in_sizes, int n_in,
                              void* d_out, int out_size) {
    const float* features = (const float*)d_in[0];
    const int*   src      = (const int*)  d_in[1];
    const int*   dst      = (const int*)  d_in[2];
    const float* W        = (const float*)d_in[3];
    const float* b        = (const float*)d_in[4];
    float*       out      = (float*)d_out;

    int n = in_sizes[0] / IN_DIM;   // 100000
    int E = in_sizes[1];            // 1600000

    const int B = 256;
    int nb = (n + SCAN_TILE - 1) / SCAN_TILE;   // 98 partial blocks

    // K0: zero degree counters
    k_zero_deg<<<(n + B - 1) / B, B>>>(n);

    // K1: in-degree histogram
    k_deg_in<<<(E + B - 1) / B, B>>>(dst, E);

    // K2: parallel 3-phase exclusive scan -> row_ptr, cursor
    k_scan_local<<<nb, 256>>>(n);
    k_scan_partials<<<1, MAX_PARTIALS>>>(nb);
    k_scan_addoff<<<(n + B - 1) / B, B>>>(n, E);

    // K3: CSR fill + out-degree histogram (2 edges/thread)
    int fillThreads = (E + 1) / 2;
    k_fill<<<(fillThreads + B - 1) / B, B>>>(src, dst, E);

    // K4: gemm + src-norm
    k_gemm_norm<<<(n + B - 1) / B, B>>>(features, W, n);

    // K5: pull aggregation + norm_dst + bias + relu (one warp per node)
    long long threads5 = (long long)n * 32;
    k_aggregate<<<(int)((threads5 + B - 1) / B), B>>>(out, b, n);
}